// round 5
// baseline (speedup 1.0000x reference)
#include <cuda_runtime.h>
#include <cuda_bf16.h>
#include <cstdint>
#include <cstddef>

#define TLEN  512
#define BATCH 128
#define EDIM  128
#define HDIM  128
#define GDIM  512   // 4*H

// Scratch (device globals — no allocation)
static __device__ float g_xp[(size_t)2 * TLEN * BATCH * GDIM];   // [dir][t][b][4H] = 256MB
static __device__ float g_pool[2 * BATCH * HDIM];

// ---------- f32x2 helpers ----------
__device__ __forceinline__ unsigned long long pk2(float lo, float hi) {
    unsigned long long r;
    asm("mov.b64 %0, {%1, %2};" : "=l"(r) : "f"(lo), "f"(hi));
    return r;
}
__device__ __forceinline__ void upk2(unsigned long long v, float& lo, float& hi) {
    asm("mov.b64 {%0, %1}, %2;" : "=f"(lo), "=f"(hi) : "l"(v));
}
__device__ __forceinline__ unsigned long long ffma2(unsigned long long a,
                                                    unsigned long long b,
                                                    unsigned long long c) {
    unsigned long long d;
    asm("fma.rn.f32x2 %0, %1, %2, %3;" : "=l"(d) : "l"(a), "l"(b), "l"(c));
    return d;
}
__device__ __forceinline__ float sig_fast(float x)  { return __fdividef(1.f, 1.f + __expf(-x)); }
__device__ __forceinline__ float tanh_fast(float x) {
    float e = __expf(-2.f * x);
    return __fdividef(1.f - e, 1.f + e);
}

// =====================================================================
// Kernel 1: embedding gather + input projection (both dirs).
// xp[dir][t][b][g] = emb[b, tsrc] . Wih[g] + bih[g] + bhh[g]
// Tile 128(b) x 128(g), K=128. grid=(4 gate tiles, 2*512), 512 thr.
// Micro-tile 4(b) x 8(g): row_grp = tid&31, col_grp = tid>>5 (warp-uniform
// -> B reads are warp-broadcast LDS). acc = 4x8 f32x2 (64 regs).
// =====================================================================
#define SA 132
#define PROJ_SMEM (2 * 128 * SA * 4)

__global__ void __launch_bounds__(512) proj_kernel(
    const int* __restrict__ x, const float* __restrict__ table,
    const float* __restrict__ Wih_f, const float* __restrict__ bih_f, const float* __restrict__ bhh_f,
    const float* __restrict__ Wih_b, const float* __restrict__ bih_b, const float* __restrict__ bhh_b)
{
    extern __shared__ float sm[];
    float* As = sm;               // [128][SA] gathered embedding rows (b, k)
    float* Bs = sm + 128 * SA;    // [128][SA] Wih rows (gate, k)
    __shared__ int   tok_s[128];
    __shared__ float bias_s[128];

    const int tid   = threadIdx.x;
    const int gtile = blockIdx.x;        // 0..3  (fast-varying: A tile L2-hot)
    const int dir   = blockIdx.y >> 9;
    const int t     = blockIdx.y & 511;

    const float* Wih = dir ? Wih_b : Wih_f;
    const float* bi  = dir ? bih_b : bih_f;
    const float* bh  = dir ? bhh_b : bhh_f;
    const int tsrc   = dir ? (TLEN - 1 - t) : t;

    if (tid < 128) {
        tok_s[tid] = x[tid * TLEN + tsrc];
        const int gg = gtile * 128 + tid;
        bias_s[tid] = bi[gg] + bh[gg];
    }
    __syncthreads();

    // Loads: one warp per table/weight row (perfectly coalesced 512B rows)
    #pragma unroll
    for (int it = 0; it < 8; ++it) {
        const int c = it * 512 + tid;
        const int i = c >> 5, kc = (c & 31) << 2;
        *(float4*)&As[i * SA + kc] = *(const float4*)&table[(size_t)tok_s[i] * EDIM + kc];
    }
    #pragma unroll
    for (int it = 0; it < 8; ++it) {
        const int c = it * 512 + tid;
        const int j = c >> 5, kc = (c & 31) << 2;
        *(float4*)&Bs[j * SA + kc] = *(const float4*)&Wih[(size_t)(gtile * 128 + j) * EDIM + kc];
    }
    __syncthreads();

    const int rg = tid & 31;    // rows 4*rg .. 4*rg+3
    const int cg = tid >> 5;    // gates 8*cg .. 8*cg+7 (warp-uniform)

    unsigned long long acc[4][8];
    #pragma unroll
    for (int r = 0; r < 4; ++r)
        #pragma unroll
        for (int j = 0; j < 8; ++j) acc[r][j] = 0ull;

    const float* Arow = &As[(rg * 4) * SA];
    const float* Brow = &Bs[(cg * 8) * SA];

    #pragma unroll 4
    for (int k2 = 0; k2 < 64; ++k2) {           // 2 k's per iteration
        unsigned long long bv[8];
        #pragma unroll
        for (int j = 0; j < 8; ++j)
            bv[j] = *(const unsigned long long*)&Brow[j * SA + k2 * 2];
        unsigned long long av[4];
        #pragma unroll
        for (int r = 0; r < 4; ++r)
            av[r] = *(const unsigned long long*)&Arow[r * SA + k2 * 2];
        #pragma unroll
        for (int r = 0; r < 4; ++r)
            #pragma unroll
            for (int j = 0; j < 8; ++j)
                acc[r][j] = ffma2(av[r], bv[j], acc[r][j]);
    }

    float* outp = g_xp + (size_t)(dir * TLEN + t) * BATCH * GDIM + gtile * 128 + cg * 8;
    #pragma unroll
    for (int r = 0; r < 4; ++r) {
        const int b = rg * 4 + r;
        float v[8];
        #pragma unroll
        for (int j = 0; j < 8; ++j) {
            float lo, hi; upk2(acc[r][j], lo, hi);
            v[j] = lo + hi + bias_s[cg * 8 + j];
        }
        float4* dst = (float4*)&outp[(size_t)b * GDIM];
        dst[0] = make_float4(v[0], v[1], v[2], v[3]);
        dst[1] = make_float4(v[4], v[5], v[6], v[7]);
    }
}

// =====================================================================
// Kernel 2: persistent LSTM scan. 128 CTAs = (dir, batch-pair); 512 thr.
// Thread g holds Whh row g as 64 bf16x2 regs; preact for 2 batch rows per
// step via fma.rn.f32x2; 256 threads do the (c,h) update. 2 bars/step.
// unroll 4 keeps live regs ~113 < 128 cap (avoid spills).
// =====================================================================
__global__ void __launch_bounds__(512) scan_kernel(
    const float* __restrict__ Whh_f, const float* __restrict__ Whh_b)
{
    __shared__ __align__(16) float h_s[2][HDIM];
    __shared__ float gact[2][GDIM];

    const int g   = threadIdx.x;
    const int dir = blockIdx.x >> 6;
    const int b0  = (blockIdx.x & 63) * 2;
    const float* Whh = dir ? Whh_b : Whh_f;

    unsigned wv[64];
    const float2* wrow = (const float2*)(Whh + (size_t)g * HDIM);
    #pragma unroll
    for (int q = 0; q < 64; ++q) {
        const float2 w = __ldg(&wrow[q]);
        const unsigned lo = (unsigned)__bfloat16_as_ushort(__float2bfloat16(w.x));
        const unsigned hi = (unsigned)__bfloat16_as_ushort(__float2bfloat16(w.y));
        wv[q] = (hi << 16) | lo;
    }

    if (g < 256) h_s[g >> 7][g & 127] = 0.f;
    float c_st = 0.f;
    float hmax = -3.4e38f;

    const float* xp = g_xp + (size_t)dir * TLEN * BATCH * GDIM;
    float x0 = __ldg(&xp[(size_t)b0 * GDIM + g]);
    float x1 = __ldg(&xp[(size_t)(b0 + 1) * GDIM + g]);
    __syncthreads();

    const int gate_type = g >> 7;   // 0:i 1:f 2:g 3:o (warp-uniform)

    for (int t = 0; t < TLEN; ++t) {
        const float cx0 = x0, cx1 = x1;
        const int tn = (t + 1 < TLEN) ? t + 1 : t;
        x0 = __ldg(&xp[((size_t)tn * BATCH + b0) * GDIM + g]);
        x1 = __ldg(&xp[((size_t)tn * BATCH + b0 + 1) * GDIM + g]);

        unsigned long long a0 = pk2(cx0, 0.f), c0 = 0ull;
        unsigned long long a1 = pk2(cx1, 0.f), c1 = 0ull;
        const ulonglong2* h40 = (const ulonglong2*)h_s[0];
        const ulonglong2* h41 = (const ulonglong2*)h_s[1];
        #pragma unroll 4
        for (int p = 0; p < 16; ++p) {   // 8 k per iter
            const unsigned u0 = wv[4*p+0], u1 = wv[4*p+1], u2 = wv[4*p+2], u3 = wv[4*p+3];
            const unsigned long long w0 = pk2(__uint_as_float(u0 << 16), __uint_as_float(u0 & 0xffff0000u));
            const unsigned long long w1 = pk2(__uint_as_float(u1 << 16), __uint_as_float(u1 & 0xffff0000u));
            const unsigned long long w2 = pk2(__uint_as_float(u2 << 16), __uint_as_float(u2 & 0xffff0000u));
            const unsigned long long w3 = pk2(__uint_as_float(u3 << 16), __uint_as_float(u3 & 0xffff0000u));
            const ulonglong2 hA = h40[2*p], hB = h40[2*p+1];
            a0 = ffma2(w0, hA.x, a0);  c0 = ffma2(w1, hA.y, c0);
            a0 = ffma2(w2, hB.x, a0);  c0 = ffma2(w3, hB.y, c0);
            const ulonglong2 hC = h41[2*p], hD = h41[2*p+1];
            a1 = ffma2(w0, hC.x, a1);  c1 = ffma2(w1, hC.y, c1);
            a1 = ffma2(w2, hD.x, a1);  c1 = ffma2(w3, hD.y, c1);
        }
        float lo, hi;
        upk2(a0, lo, hi); float s0 = lo + hi;
        upk2(c0, lo, hi); s0 += lo + hi;
        upk2(a1, lo, hi); float s1 = lo + hi;
        upk2(c1, lo, hi); s1 += lo + hi;

        float v0, v1;
        if (gate_type == 2) { v0 = tanh_fast(s0); v1 = tanh_fast(s1); }
        else                { v0 = sig_fast(s0);  v1 = sig_fast(s1); }
        gact[0][g] = v0;
        gact[1][g] = v1;
        __syncthreads();

        if (g < 256) {
            const int bb = g >> 7, u = g & 127;
            const float iv = gact[bb][u];
            const float fv = gact[bb][128 + u];
            const float gv = gact[bb][256 + u];
            const float ov = gact[bb][384 + u];
            c_st = fv * c_st + iv * gv;
            const float hn = ov * tanh_fast(c_st);
            hmax = fmaxf(hmax, hn);
            h_s[bb][u] = hn;
        }
        __syncthreads();
    }

    if (g < 256) {
        const int bb = g >> 7, u = g & 127;
        g_pool[((size_t)dir * BATCH + b0 + bb) * HDIM + u] = hmax;
    }
}

// =====================================================================
// Kernel 3: MLP head. grid=128 (batch), 64 threads (hidden units).
// =====================================================================
__global__ void __launch_bounds__(64) mlp_kernel(
    const float* __restrict__ W1, const float* __restrict__ b1,
    const float* __restrict__ W2, const float* __restrict__ b2,
    float* __restrict__ out)
{
    __shared__ __align__(16) float pv[256];
    __shared__ float red[64];
    const int b = blockIdx.x;
    const int j = threadIdx.x;

    for (int k = j; k < 256; k += 64) {
        const int dir = k >> 7, u = k & 127;
        pv[k] = g_pool[((size_t)dir * BATCH + b) * HDIM + u];
    }
    __syncthreads();

    float acc = b1[j];
    const float4* w4 = (const float4*)(W1 + (size_t)j * 256);
    const float4* p4 = (const float4*)pv;
    #pragma unroll 8
    for (int k = 0; k < 64; ++k) {
        const float4 w = w4[k], p = p4[k];
        acc += w.x * p.x + w.y * p.y + w.z * p.z + w.w * p.w;
    }
    red[j] = fmaxf(acc, 0.f) * W2[j];
    __syncthreads();

    if (j == 0) {
        float s = b2[0];
        #pragma unroll
        for (int k = 0; k < 64; ++k) s += red[k];
        out[b] = 1.f / (1.f + expf(-s));
    }
}

// =====================================================================
extern "C" void kernel_launch(void* const* d_in, const int* in_sizes, int n_in,
                              void* d_out, int out_size) {
    const int*   x     = (const int*)d_in[0];
    const float* table = (const float*)d_in[1];
    const float* Wih_f = (const float*)d_in[2];
    const float* Whh_f = (const float*)d_in[3];
    const float* bih_f = (const float*)d_in[4];
    const float* bhh_f = (const float*)d_in[5];
    const float* Wih_b = (const float*)d_in[6];
    const float* Whh_b = (const float*)d_in[7];
    const float* bih_b = (const float*)d_in[8];
    const float* bhh_b = (const float*)d_in[9];
    const float* W1    = (const float*)d_in[10];
    const float* b1    = (const float*)d_in[11];
    const float* W2    = (const float*)d_in[12];
    const float* b2    = (const float*)d_in[13];
    float* out = (float*)d_out;

    cudaFuncSetAttribute(proj_kernel, cudaFuncAttributeMaxDynamicSharedMemorySize, PROJ_SMEM);

    dim3 pg(4, 2 * TLEN);
    proj_kernel<<<pg, 512, PROJ_SMEM>>>(x, table, Wih_f, bih_f, bhh_f, Wih_b, bih_b, bhh_b);
    scan_kernel<<<128, 512>>>(Whh_f, Whh_b);
    mlp_kernel<<<128, 64>>>(W1, b1, W2, b2, out);
}

// round 6
// speedup vs baseline: 2.8068x; 2.8068x over previous
#include <cuda_runtime.h>
#include <cuda_bf16.h>
#include <cstdint>
#include <cstddef>

#define TLEN  512
#define BATCH 128
#define EDIM  128
#define HDIM  128
#define GDIM  512   // 4*H

// Scratch (device globals — no allocation). xp layout: [dir][t][gate][batch], bf16.
static __device__ __nv_bfloat16 g_xp[(size_t)2 * TLEN * GDIM * BATCH];
static __device__ float g_pool[2 * BATCH * HDIM];

// ---------- helpers ----------
__device__ __forceinline__ unsigned pack2(float lo, float hi) {   // bf16x2 {hi,lo}
    unsigned r;
    asm("cvt.rn.bf16x2.f32 %0, %1, %2;" : "=r"(r) : "f"(hi), "f"(lo));
    return r;
}
__device__ __forceinline__ float tanh_ap(float x) {
    float y; asm("tanh.approx.f32 %0, %1;" : "=f"(y) : "f"(x)); return y;
}
__device__ __forceinline__ float sig_ap(float x) { return 0.5f * tanh_ap(0.5f * x) + 0.5f; }

__device__ __forceinline__ void mma16816(float& d0, float& d1, float& d2, float& d3,
                                         unsigned a0, unsigned a1, unsigned a2, unsigned a3,
                                         unsigned b0, unsigned b1) {
    asm("mma.sync.aligned.m16n8k16.row.col.f32.bf16.bf16.f32 "
        "{%0,%1,%2,%3},{%4,%5,%6,%7},{%8,%9},{%0,%1,%2,%3};"
        : "+f"(d0), "+f"(d1), "+f"(d2), "+f"(d3)
        : "r"(a0), "r"(a1), "r"(a2), "r"(a3), "r"(b0), "r"(b1));
}

// =====================================================================
// Kernel 1: embedding gather + input projection, bf16 mma.
// C[g=128][b=128] = Wih_tile[g][e] * embT[e][b], k=E=128, + bias, -> bf16 xp.
// grid=(4 gtiles, 2*512), 256 thr (8 warps; warp w = m-tile w).
// smem: Wsm[128][136] bf16, Esm[128][136] bf16 (B col-major = [b][e] natural).
// =====================================================================
#define PJ_STRIDE 136
#define PJ_SMEM (2 * 128 * PJ_STRIDE * 2)   // 69632 B

__global__ void __launch_bounds__(256, 2) proj_kernel(
    const int* __restrict__ x, const float* __restrict__ table,
    const float* __restrict__ Wih_f, const float* __restrict__ bih_f, const float* __restrict__ bhh_f,
    const float* __restrict__ Wih_b, const float* __restrict__ bih_b, const float* __restrict__ bhh_b)
{
    extern __shared__ char dynsm[];
    __nv_bfloat16* Wsm = (__nv_bfloat16*)dynsm;           // [128][136]
    __nv_bfloat16* Esm = Wsm + 128 * PJ_STRIDE;           // [128][136]
    __shared__ int   tok_s[128];
    __shared__ float bias_s[128];

    const int tid  = threadIdx.x, lane = tid & 31, w = tid >> 5;
    const int gtile = blockIdx.x;
    const int dir   = blockIdx.y >> 9;
    const int t     = blockIdx.y & 511;
    const float* Wih = dir ? Wih_b : Wih_f;
    const float* bi  = dir ? bih_b : bih_f;
    const float* bh  = dir ? bhh_b : bhh_f;
    const int tsrc   = dir ? (TLEN - 1 - t) : t;

    if (tid < 128) {
        tok_s[tid] = x[tid * TLEN + tsrc];
        const int gg = gtile * 128 + tid;
        bias_s[tid] = bi[gg] + bh[gg];
    }
    __syncthreads();

    #pragma unroll
    for (int it = 0; it < 16; ++it) {
        const int idx = it * 256 + tid;
        const int rb = idx >> 5, q = idx & 31;
        const float4 v = __ldg((const float4*)(table + (size_t)tok_s[rb] * EDIM) + q);
        *(uint2*)&Esm[rb * PJ_STRIDE + q * 4] = make_uint2(pack2(v.x, v.y), pack2(v.z, v.w));
    }
    #pragma unroll
    for (int it = 0; it < 16; ++it) {
        const int idx = it * 256 + tid;
        const int rg = idx >> 5, q = idx & 31;
        const float4 v = __ldg((const float4*)(Wih + (size_t)(gtile * 128 + rg) * EDIM) + q);
        *(uint2*)&Wsm[rg * PJ_STRIDE + q * 4] = make_uint2(pack2(v.x, v.y), pack2(v.z, v.w));
    }
    __syncthreads();

    const int kq = (lane & 3) * 2;
    const int r0 = w * 16 + (lane >> 2);

    unsigned Afr[8][4];
    #pragma unroll
    for (int kt = 0; kt < 8; ++kt) {
        const int k = kt * 16 + kq;
        Afr[kt][0] = *(const unsigned*)&Wsm[r0 * PJ_STRIDE + k];
        Afr[kt][1] = *(const unsigned*)&Wsm[(r0 + 8) * PJ_STRIDE + k];
        Afr[kt][2] = *(const unsigned*)&Wsm[r0 * PJ_STRIDE + k + 8];
        Afr[kt][3] = *(const unsigned*)&Wsm[(r0 + 8) * PJ_STRIDE + k + 8];
    }

    float D[16][4];
    #pragma unroll
    for (int nt = 0; nt < 16; ++nt)
        #pragma unroll
        for (int e = 0; e < 4; ++e) D[nt][e] = 0.f;

    #pragma unroll
    for (int kt = 0; kt < 8; ++kt) {
        #pragma unroll
        for (int nt = 0; nt < 16; ++nt) {
            const int n = nt * 8 + (lane >> 2);
            const unsigned b0 = *(const unsigned*)&Esm[n * PJ_STRIDE + kt * 16 + kq];
            const unsigned b1 = *(const unsigned*)&Esm[n * PJ_STRIDE + kt * 16 + kq + 8];
            mma16816(D[nt][0], D[nt][1], D[nt][2], D[nt][3],
                     Afr[kt][0], Afr[kt][1], Afr[kt][2], Afr[kt][3], b0, b1);
        }
    }

    const float bias0 = bias_s[w * 16 + (lane >> 2)];
    const float bias1 = bias_s[w * 16 + (lane >> 2) + 8];
    __nv_bfloat16* outp = g_xp + ((size_t)(dir * TLEN + t) * GDIM + gtile * 128) * BATCH;
    #pragma unroll
    for (int nt = 0; nt < 16; ++nt) {
        const int bc = nt * 8 + kq;
        const unsigned w0 = pack2(D[nt][0] + bias0, D[nt][1] + bias0);
        const unsigned w1 = pack2(D[nt][2] + bias1, D[nt][3] + bias1);
        *(unsigned*)&outp[(size_t)r0 * BATCH + bc]       = w0;
        *(unsigned*)&outp[(size_t)(r0 + 8) * BATCH + bc] = w1;
    }
}

// =====================================================================
// Kernel 2: LSTM scan with mma. 32 CTAs = 2 dirs x 16 slices of 8 batch.
// 256 thr (8 warps); warp w owns gate rows [w*64, w*64+64) -> activation
// choice warp-uniform (w>>1: 0,1,3=sigmoid, 2=tanh).
// Whh bf16 in smem; A frags preloaded to 128 regs/thread (loop-invariant).
// Per step: D=xp (prefetched), 8x(2 LDS + 4 mma), act+STS, bar, update, bar.
// =====================================================================
#define SC_WSTRIDE 136       // Whh smem row stride (bf16)
#define SC_SMEM (512 * SC_WSTRIDE * 2)   // 139264 B dynamic
#define GA 516               // gact row stride (floats)

__global__ void __launch_bounds__(256, 1) scan_kernel(
    const float* __restrict__ Whh_f, const float* __restrict__ Whh_b)
{
    extern __shared__ char dynsm[];
    __nv_bfloat16* Wsm = (__nv_bfloat16*)dynsm;   // [512][136]
    __shared__ float gact[8 * GA];
    __shared__ __nv_bfloat16 h_sm[8 * SC_WSTRIDE];

    const int tid  = threadIdx.x, lane = tid & 31, w = tid >> 5;
    const int dir  = blockIdx.x >> 4;
    const int bbase = (blockIdx.x & 15) * 8;
    const float* Whh = dir ? Whh_b : Whh_f;

    // Load + convert Whh to bf16 smem (once)
    for (int it = 0; it < 64; ++it) {
        const int idx = it * 256 + tid;
        const int row = idx >> 5, q = idx & 31;
        const float4 v = __ldg((const float4*)(Whh + (size_t)row * HDIM) + q);
        *(uint2*)&Wsm[row * SC_WSTRIDE + q * 4] = make_uint2(pack2(v.x, v.y), pack2(v.z, v.w));
    }
    for (int i = tid; i < 8 * SC_WSTRIDE; i += 256) h_sm[i] = __float2bfloat16(0.f);
    __syncthreads();

    // Preload A fragments (Whh rows for this warp) — loop-invariant, 128 regs
    const int kq = (lane & 3) * 2;
    unsigned A[4][8][4];
    #pragma unroll
    for (int i = 0; i < 4; ++i) {
        const int r0 = w * 64 + i * 16 + (lane >> 2);
        #pragma unroll
        for (int kt = 0; kt < 8; ++kt) {
            const int k = kt * 16 + kq;
            A[i][kt][0] = *(const unsigned*)&Wsm[r0 * SC_WSTRIDE + k];
            A[i][kt][1] = *(const unsigned*)&Wsm[(r0 + 8) * SC_WSTRIDE + k];
            A[i][kt][2] = *(const unsigned*)&Wsm[r0 * SC_WSTRIDE + k + 8];
            A[i][kt][3] = *(const unsigned*)&Wsm[(r0 + 8) * SC_WSTRIDE + k + 8];
        }
    }

    // xp pointers: xp[dir][t][g][b], this thread reads batch pair (bbase+kq)
    size_t off0[4], off1[4];
    #pragma unroll
    for (int i = 0; i < 4; ++i) {
        const int gr = w * 64 + i * 16 + (lane >> 2);
        off0[i] = (size_t)gr * BATCH + bbase + kq;
        off1[i] = off0[i] + 8 * BATCH;
    }
    const __nv_bfloat16* xpd = g_xp + (size_t)dir * TLEN * GDIM * BATCH;

    unsigned xb0[4], xb1[4];
    #pragma unroll
    for (int i = 0; i < 4; ++i) {
        xb0[i] = *(const unsigned*)(xpd + off0[i]);
        xb1[i] = *(const unsigned*)(xpd + off1[i]);
    }

    const int region = w >> 1;           // 0:i 1:f 2:g 3:o
    const int uu = tid & 127, bq = tid >> 7;
    float cst[4]  = {0.f, 0.f, 0.f, 0.f};
    float hmax[4] = {-3.4e38f, -3.4e38f, -3.4e38f, -3.4e38f};

    for (int t = 0; t < TLEN; ++t) {
        // D init from xp (bf16 pairs -> fp32)
        float D[4][4];
        #pragma unroll
        for (int i = 0; i < 4; ++i) {
            const float2 p0 = __bfloat1622float2(*(const __nv_bfloat162*)&xb0[i]);
            const float2 p1 = __bfloat1622float2(*(const __nv_bfloat162*)&xb1[i]);
            D[i][0] = p0.x; D[i][1] = p0.y; D[i][2] = p1.x; D[i][3] = p1.y;
        }
        // prefetch next t's xp
        const __nv_bfloat16* xnext = xpd + (size_t)((t + 1 < TLEN) ? t + 1 : t) * GDIM * BATCH;
        #pragma unroll
        for (int i = 0; i < 4; ++i) {
            xb0[i] = *(const unsigned*)(xnext + off0[i]);
            xb1[i] = *(const unsigned*)(xnext + off1[i]);
        }

        // h @ Whh^T : B frags from h_sm, 32 mma
        #pragma unroll
        for (int kt = 0; kt < 8; ++kt) {
            const int k = kt * 16 + kq;
            const unsigned b0 = *(const unsigned*)&h_sm[(lane >> 2) * SC_WSTRIDE + k];
            const unsigned b1 = *(const unsigned*)&h_sm[(lane >> 2) * SC_WSTRIDE + k + 8];
            #pragma unroll
            for (int i = 0; i < 4; ++i)
                mma16816(D[i][0], D[i][1], D[i][2], D[i][3],
                         A[i][kt][0], A[i][kt][1], A[i][kt][2], A[i][kt][3], b0, b1);
        }

        // activations (warp-uniform choice) + scatter to gact[b][g]
        #pragma unroll
        for (int i = 0; i < 4; ++i) {
            const int gr = w * 64 + i * 16 + (lane >> 2);
            #pragma unroll
            for (int e = 0; e < 4; ++e) {
                const float v = (region == 2) ? tanh_ap(D[i][e]) : sig_ap(D[i][e]);
                const int g = gr + (e >> 1) * 8;
                const int b = kq + (e & 1);
                gact[b * GA + g] = v;
            }
        }
        __syncthreads();

        // elementwise update: thread handles (u = uu, b = bq + 2m)
        #pragma unroll
        for (int m = 0; m < 4; ++m) {
            const int b = bq + 2 * m;
            const float iv = gact[b * GA + uu];
            const float fv = gact[b * GA + 128 + uu];
            const float gv = gact[b * GA + 256 + uu];
            const float ov = gact[b * GA + 384 + uu];
            cst[m] = fv * cst[m] + iv * gv;
            const float hn = ov * tanh_ap(cst[m]);
            hmax[m] = fmaxf(hmax[m], hn);
            h_sm[b * SC_WSTRIDE + uu] = __float2bfloat16(hn);
        }
        __syncthreads();
    }

    #pragma unroll
    for (int m = 0; m < 4; ++m)
        g_pool[((size_t)dir * BATCH + bbase + bq + 2 * m) * HDIM + uu] = hmax[m];
}

// =====================================================================
// Kernel 3: MLP head. grid=128 (batch), 64 threads (hidden units).
// =====================================================================
__global__ void __launch_bounds__(64) mlp_kernel(
    const float* __restrict__ W1, const float* __restrict__ b1,
    const float* __restrict__ W2, const float* __restrict__ b2,
    float* __restrict__ out)
{
    __shared__ __align__(16) float pv[256];
    __shared__ float red[64];
    const int b = blockIdx.x;
    const int j = threadIdx.x;

    for (int k = j; k < 256; k += 64) {
        const int dir = k >> 7, u = k & 127;
        pv[k] = g_pool[((size_t)dir * BATCH + b) * HDIM + u];
    }
    __syncthreads();

    float acc = b1[j];
    const float4* w4 = (const float4*)(W1 + (size_t)j * 256);
    const float4* p4 = (const float4*)pv;
    #pragma unroll 8
    for (int k = 0; k < 64; ++k) {
        const float4 wv = w4[k], p = p4[k];
        acc += wv.x * p.x + wv.y * p.y + wv.z * p.z + wv.w * p.w;
    }
    red[j] = fmaxf(acc, 0.f) * W2[j];
    __syncthreads();

    if (j == 0) {
        float s = b2[0];
        #pragma unroll
        for (int k = 0; k < 64; ++k) s += red[k];
        out[b] = 1.f / (1.f + expf(-s));
    }
}

// =====================================================================
extern "C" void kernel_launch(void* const* d_in, const int* in_sizes, int n_in,
                              void* d_out, int out_size) {
    const int*   x     = (const int*)d_in[0];
    const float* table = (const float*)d_in[1];
    const float* Wih_f = (const float*)d_in[2];
    const float* Whh_f = (const float*)d_in[3];
    const float* bih_f = (const float*)d_in[4];
    const float* bhh_f = (const float*)d_in[5];
    const float* Wih_b = (const float*)d_in[6];
    const float* Whh_b = (const float*)d_in[7];
    const float* bih_b = (const float*)d_in[8];
    const float* bhh_b = (const float*)d_in[9];
    const float* W1    = (const float*)d_in[10];
    const float* b1    = (const float*)d_in[11];
    const float* W2    = (const float*)d_in[12];
    const float* b2    = (const float*)d_in[13];
    float* out = (float*)d_out;

    cudaFuncSetAttribute(proj_kernel, cudaFuncAttributeMaxDynamicSharedMemorySize, PJ_SMEM);
    cudaFuncSetAttribute(scan_kernel, cudaFuncAttributeMaxDynamicSharedMemorySize, SC_SMEM);

    dim3 pg(4, 2 * TLEN);
    proj_kernel<<<pg, 256, PJ_SMEM>>>(x, table, Wih_f, bih_f, bhh_f, Wih_b, bih_b, bhh_b);
    scan_kernel<<<32, 256, SC_SMEM>>>(Whh_f, Whh_b);
    mlp_kernel<<<128, 64>>>(W1, b1, W2, b2, out);
}

// round 7
// speedup vs baseline: 3.6839x; 1.3125x over previous
#include <cuda_runtime.h>
#include <cuda_bf16.h>
#include <cstdint>
#include <cstddef>

#define TLEN  512
#define BATCH 128
#define EDIM  128
#define HDIM  128
#define GDIM  512   // 4*H

// Scratch (device globals — no allocation). xp layout: [dir][t][gate][batch], bf16.
static __device__ __nv_bfloat16 g_xp[(size_t)2 * TLEN * GDIM * BATCH];
static __device__ float g_pool[2 * BATCH * HDIM];

// ---------- helpers ----------
__device__ __forceinline__ unsigned pack2(float lo, float hi) {   // bf16x2, lo in low half
    unsigned r;
    asm("cvt.rn.bf16x2.f32 %0, %1, %2;" : "=r"(r) : "f"(hi), "f"(lo));
    return r;
}
__device__ __forceinline__ float2 bup2(unsigned v) {
    __nv_bfloat162 b = *reinterpret_cast<__nv_bfloat162*>(&v);
    return __bfloat1622float2(b);
}
#define BF_HALF2 0x3F003F00u
__device__ __forceinline__ unsigned bmul2(unsigned a, unsigned b) {
    unsigned d; asm("mul.rn.bf16x2 %0,%1,%2;" : "=r"(d) : "r"(a), "r"(b)); return d;
}
__device__ __forceinline__ unsigned bfma2(unsigned a, unsigned b, unsigned c) {
    unsigned d; asm("fma.rn.bf16x2 %0,%1,%2,%3;" : "=r"(d) : "r"(a), "r"(b), "r"(c)); return d;
}
__device__ __forceinline__ unsigned btanh2(unsigned a) {
    unsigned d; asm("tanh.approx.bf16x2 %0,%1;" : "=r"(d) : "r"(a)); return d;
}
__device__ __forceinline__ unsigned bsig2(unsigned x) {   // sigmoid = 0.5*tanh(0.5x)+0.5
    return bfma2(btanh2(bmul2(x, BF_HALF2)), BF_HALF2, BF_HALF2);
}
__device__ __forceinline__ float tanh_ap(float x) {
    float y; asm("tanh.approx.f32 %0, %1;" : "=f"(y) : "f"(x)); return y;
}

__device__ __forceinline__ void mma16816(float& d0, float& d1, float& d2, float& d3,
                                         unsigned a0, unsigned a1, unsigned a2, unsigned a3,
                                         unsigned b0, unsigned b1) {
    asm("mma.sync.aligned.m16n8k16.row.col.f32.bf16.bf16.f32 "
        "{%0,%1,%2,%3},{%4,%5,%6,%7},{%8,%9},{%0,%1,%2,%3};"
        : "+f"(d0), "+f"(d1), "+f"(d2), "+f"(d3)
        : "r"(a0), "r"(a1), "r"(a2), "r"(a3), "r"(b0), "r"(b1));
}
__device__ __forceinline__ unsigned sptr(const void* p) {
    return (unsigned)__cvta_generic_to_shared(p);
}
__device__ __forceinline__ void ldsm4(unsigned& r0, unsigned& r1, unsigned& r2, unsigned& r3,
                                      unsigned addr) {
    asm volatile("ldmatrix.sync.aligned.m8n8.x4.shared.b16 {%0,%1,%2,%3}, [%4];"
                 : "=r"(r0), "=r"(r1), "=r"(r2), "=r"(r3) : "r"(addr));
}
__device__ __forceinline__ void ldsm4t(unsigned& r0, unsigned& r1, unsigned& r2, unsigned& r3,
                                       unsigned addr) {
    asm volatile("ldmatrix.sync.aligned.m8n8.x4.trans.shared.b16 {%0,%1,%2,%3}, [%4];"
                 : "=r"(r0), "=r"(r1), "=r"(r2), "=r"(r3) : "r"(addr));
}

// =====================================================================
// Kernel 1: embedding gather + input projection, bf16 mma + ldmatrix.
// C[g=128][b=128] = Wih_tile[g][e] * embT[e][b] + bias -> bf16 xp[g][b].
// grid=(4 gtiles, 2*512), 256 thr; warp w = m-tile (16 gates) x n=128.
// =====================================================================
#define PJ_STRIDE 136
#define PJ_SMEM (2 * 128 * PJ_STRIDE * 2)   // 69632 B

__global__ void __launch_bounds__(256, 2) proj_kernel(
    const int* __restrict__ x, const float* __restrict__ table,
    const float* __restrict__ Wih_f, const float* __restrict__ bih_f, const float* __restrict__ bhh_f,
    const float* __restrict__ Wih_b, const float* __restrict__ bih_b, const float* __restrict__ bhh_b)
{
    extern __shared__ char dynsm[];
    __nv_bfloat16* Wsm = (__nv_bfloat16*)dynsm;           // [128][136]
    __nv_bfloat16* Esm = Wsm + 128 * PJ_STRIDE;           // [128][136]
    __shared__ int   tok_s[128];
    __shared__ float bias_s[128];

    const int tid  = threadIdx.x, lane = tid & 31, w = tid >> 5;
    const int gtile = blockIdx.x;
    const int dir   = blockIdx.y >> 9;
    const int t     = blockIdx.y & 511;
    const float* Wih = dir ? Wih_b : Wih_f;
    const float* bi  = dir ? bih_b : bih_f;
    const float* bh  = dir ? bhh_b : bhh_f;
    const int tsrc   = dir ? (TLEN - 1 - t) : t;

    if (tid < 128) {
        tok_s[tid] = x[tid * TLEN + tsrc];
        const int gg = gtile * 128 + tid;
        bias_s[tid] = bi[gg] + bh[gg];
    }
    __syncthreads();

    #pragma unroll
    for (int it = 0; it < 16; ++it) {
        const int idx = it * 256 + tid;
        const int rb = idx >> 5, q = idx & 31;
        const float4 v = __ldg((const float4*)(table + (size_t)tok_s[rb] * EDIM) + q);
        *(uint2*)&Esm[rb * PJ_STRIDE + q * 4] = make_uint2(pack2(v.x, v.y), pack2(v.z, v.w));
    }
    #pragma unroll
    for (int it = 0; it < 16; ++it) {
        const int idx = it * 256 + tid;
        const int rg = idx >> 5, q = idx & 31;
        const float4 v = __ldg((const float4*)(Wih + (size_t)(gtile * 128 + rg) * EDIM) + q);
        *(uint2*)&Wsm[rg * PJ_STRIDE + q * 4] = make_uint2(pack2(v.x, v.y), pack2(v.z, v.w));
    }
    __syncthreads();

    const int li = lane & 7, grp = lane >> 3;

    // A preload: 8 ldsm.x4 (frag a0..a3 per kt)
    unsigned Afr[8][4];
    {
        const unsigned wbase = sptr(Wsm) +
            (((w * 16 + (grp & 1) * 8 + li) * PJ_STRIDE + (grp >> 1) * 8) << 1);
        #pragma unroll
        for (int kt = 0; kt < 8; ++kt)
            ldsm4(Afr[kt][0], Afr[kt][1], Afr[kt][2], Afr[kt][3], wbase + kt * 32);
    }

    float D[16][4];
    #pragma unroll
    for (int nt = 0; nt < 16; ++nt)
        #pragma unroll
        for (int e = 0; e < 4; ++e) D[nt][e] = 0.f;

    // B loads: ldsm.x4 gives (b0,b1) for kt=2p and kt=2p+1
    const unsigned ebase = sptr(Esm) + ((li * PJ_STRIDE + grp * 8) << 1);
    #pragma unroll
    for (int p = 0; p < 4; ++p) {
        #pragma unroll
        for (int nt = 0; nt < 16; ++nt) {
            unsigned b0a, b1a, b0b, b1b;
            ldsm4(b0a, b1a, b0b, b1b, ebase + nt * (8 * PJ_STRIDE * 2) + p * 64);
            mma16816(D[nt][0], D[nt][1], D[nt][2], D[nt][3],
                     Afr[2*p][0], Afr[2*p][1], Afr[2*p][2], Afr[2*p][3], b0a, b1a);
            mma16816(D[nt][0], D[nt][1], D[nt][2], D[nt][3],
                     Afr[2*p+1][0], Afr[2*p+1][1], Afr[2*p+1][2], Afr[2*p+1][3], b0b, b1b);
        }
    }

    const int r0 = w * 16 + (lane >> 2);
    const int kq = (lane & 3) * 2;
    const float bias0 = bias_s[r0];
    const float bias1 = bias_s[r0 + 8];
    __nv_bfloat16* outp = g_xp + ((size_t)(dir * TLEN + t) * GDIM + gtile * 128) * BATCH;
    #pragma unroll
    for (int nt = 0; nt < 16; ++nt) {
        const int bc = nt * 8 + kq;
        *(unsigned*)&outp[(size_t)r0 * BATCH + bc]       = pack2(D[nt][0] + bias0, D[nt][1] + bias0);
        *(unsigned*)&outp[(size_t)(r0 + 8) * BATCH + bc] = pack2(D[nt][2] + bias1, D[nt][3] + bias1);
    }
}

// =====================================================================
// Kernel 2: fused-gate LSTM scan. 32 CTAs = 2 dirs x 16 slices of 8 batch.
// 8 warps; warp w owns u in [16w,16w+16). 4 mma-chains (i,f,g,o) land all
// gates of (u,b) in the SAME thread: c,h,hmax in regs, no gate exchange,
// 1 barrier/step, h ping-pong [u][8b] bf16 read via ldmatrix.x4.trans.
// =====================================================================
#define SC_WSTRIDE 136
#define SC_SMEM (512 * SC_WSTRIDE * 2)   // 139264 B dynamic

__global__ void __launch_bounds__(256, 1) scan_kernel(
    const float* __restrict__ Whh_f, const float* __restrict__ Whh_b)
{
    extern __shared__ char dynsm[];
    __nv_bfloat16* Wsm = (__nv_bfloat16*)dynsm;   // [512][136]
    __shared__ __align__(16) __nv_bfloat16 h_pp[2][HDIM][8];   // ping-pong, [u][b]

    const int tid  = threadIdx.x, lane = tid & 31, w = tid >> 5;
    const int dir  = blockIdx.x >> 4;
    const int bbase = (blockIdx.x & 15) * 8;
    const float* Whh = dir ? Whh_b : Whh_f;

    // Whh -> bf16 smem
    #pragma unroll 4
    for (int it = 0; it < 64; ++it) {
        const int idx = it * 256 + tid;
        const int row = idx >> 5, q = idx & 31;
        const float4 v = __ldg((const float4*)(Whh + (size_t)row * HDIM) + q);
        *(uint2*)&Wsm[row * SC_WSTRIDE + q * 4] = make_uint2(pack2(v.x, v.y), pack2(v.z, v.w));
    }
    for (int i = tid; i < 2 * HDIM * 8; i += 256) ((__nv_bfloat16*)h_pp)[i] = __float2bfloat16(0.f);
    __syncthreads();

    // A frags: 4 gates x 8 kt, rows q*128 + [16w,16w+16)
    const int li = lane & 7, grp = lane >> 3;
    unsigned A[4][8][4];
    #pragma unroll
    for (int q = 0; q < 4; ++q) {
        const unsigned base = sptr(Wsm) +
            (((q * 128 + w * 16 + (grp & 1) * 8 + li) * SC_WSTRIDE + (grp >> 1) * 8) << 1);
        #pragma unroll
        for (int kt = 0; kt < 8; ++kt)
            ldsm4(A[q][kt][0], A[q][kt][1], A[q][kt][2], A[q][kt][3], base + kt * 32);
    }

    // xp offsets: thread element rows u = 16w + (lane>>2) (+8), cols b pair 2*(lane&3)
    const int ur = w * 16 + (lane >> 2);
    const int cb = (lane & 3) * 2;
    const __nv_bfloat16* xpd = g_xp + (size_t)dir * TLEN * GDIM * BATCH;
    size_t off[4];
    #pragma unroll
    for (int q = 0; q < 4; ++q) off[q] = (size_t)(q * 128 + ur) * BATCH + bbase + cb;

    unsigned px0[4], px1[4];
    #pragma unroll
    for (int q = 0; q < 4; ++q) {
        px0[q] = *(const unsigned*)(xpd + off[q]);
        px1[q] = *(const unsigned*)(xpd + off[q] + 8 * BATCH);
    }

    float cst[4]  = {0.f, 0.f, 0.f, 0.f};
    float hmax[4] = {-3.4e38f, -3.4e38f, -3.4e38f, -3.4e38f};

    for (int t = 0; t < TLEN; ++t) {
        // D init from xp
        float D[4][4];
        #pragma unroll
        for (int q = 0; q < 4; ++q) {
            const float2 p0 = bup2(px0[q]), p1 = bup2(px1[q]);
            D[q][0] = p0.x; D[q][1] = p0.y; D[q][2] = p1.x; D[q][3] = p1.y;
        }
        // prefetch next xp
        const __nv_bfloat16* xn = xpd + (size_t)((t + 1 < TLEN) ? t + 1 : t) * GDIM * BATCH;
        #pragma unroll
        for (int q = 0; q < 4; ++q) {
            px0[q] = *(const unsigned*)(xn + off[q]);
            px1[q] = *(const unsigned*)(xn + off[q] + 8 * BATCH);
        }

        // B frags from h ping buffer (trans ldmatrix, 16B rows)
        const __nv_bfloat16* hb = &h_pp[t & 1][0][0];
        unsigned B[8][2];
        const unsigned hbase = sptr(hb) + lane * 16;
        #pragma unroll
        for (int j = 0; j < 4; ++j)
            ldsm4t(B[2*j][0], B[2*j][1], B[2*j+1][0], B[2*j+1][1], hbase + j * 512);

        // 4 independent mma chains (one per gate)
        #pragma unroll
        for (int kt = 0; kt < 8; ++kt)
            #pragma unroll
            for (int q = 0; q < 4; ++q)
                mma16816(D[q][0], D[q][1], D[q][2], D[q][3],
                         A[q][kt][0], A[q][kt][1], A[q][kt][2], A[q][kt][3],
                         B[kt][0], B[kt][1]);

        // packed bf16x2 activations; c stays fp32
        unsigned I0 = bsig2(pack2(D[0][0], D[0][1])), I1 = bsig2(pack2(D[0][2], D[0][3]));
        unsigned F0 = bsig2(pack2(D[1][0], D[1][1])), F1 = bsig2(pack2(D[1][2], D[1][3]));
        unsigned G0 = btanh2(pack2(D[2][0], D[2][1])), G1 = btanh2(pack2(D[2][2], D[2][3]));
        unsigned O0 = bsig2(pack2(D[3][0], D[3][1])), O1 = bsig2(pack2(D[3][2], D[3][3]));

        const float2 iv0 = bup2(I0), iv1 = bup2(I1);
        const float2 fv0 = bup2(F0), fv1 = bup2(F1);
        const float2 gv0 = bup2(G0), gv1 = bup2(G1);
        cst[0] = fv0.x * cst[0] + iv0.x * gv0.x;
        cst[1] = fv0.y * cst[1] + iv0.y * gv0.y;
        cst[2] = fv1.x * cst[2] + iv1.x * gv1.x;
        cst[3] = fv1.y * cst[3] + iv1.y * gv1.y;

        const unsigned T0 = btanh2(pack2(cst[0], cst[1]));
        const unsigned T1 = btanh2(pack2(cst[2], cst[3]));
        const unsigned H0 = bmul2(O0, T0);
        const unsigned H1 = bmul2(O1, T1);

        const float2 h0 = bup2(H0), h1 = bup2(H1);
        hmax[0] = fmaxf(hmax[0], h0.x);
        hmax[1] = fmaxf(hmax[1], h0.y);
        hmax[2] = fmaxf(hmax[2], h1.x);
        hmax[3] = fmaxf(hmax[3], h1.y);

        __nv_bfloat16* hw = &h_pp[(t + 1) & 1][0][0];
        *(unsigned*)&hw[ur * 8 + cb]       = H0;
        *(unsigned*)&hw[(ur + 8) * 8 + cb] = H1;
        __syncthreads();
    }

    g_pool[((size_t)dir * BATCH + bbase + cb)     * HDIM + ur]     = hmax[0];
    g_pool[((size_t)dir * BATCH + bbase + cb + 1) * HDIM + ur]     = hmax[1];
    g_pool[((size_t)dir * BATCH + bbase + cb)     * HDIM + ur + 8] = hmax[2];
    g_pool[((size_t)dir * BATCH + bbase + cb + 1) * HDIM + ur + 8] = hmax[3];
}

// =====================================================================
// Kernel 3: MLP head. grid=128 (batch), 64 threads (hidden units).
// =====================================================================
__global__ void __launch_bounds__(64) mlp_kernel(
    const float* __restrict__ W1, const float* __restrict__ b1,
    const float* __restrict__ W2, const float* __restrict__ b2,
    float* __restrict__ out)
{
    __shared__ __align__(16) float pv[256];
    __shared__ float red[64];
    const int b = blockIdx.x;
    const int j = threadIdx.x;

    for (int k = j; k < 256; k += 64) {
        const int dir = k >> 7, u = k & 127;
        pv[k] = g_pool[((size_t)dir * BATCH + b) * HDIM + u];
    }
    __syncthreads();

    float acc = b1[j];
    const float4* w4 = (const float4*)(W1 + (size_t)j * 256);
    const float4* p4 = (const float4*)pv;
    #pragma unroll 8
    for (int k = 0; k < 64; ++k) {
        const float4 wv = w4[k], p = p4[k];
        acc += wv.x * p.x + wv.y * p.y + wv.z * p.z + wv.w * p.w;
    }
    red[j] = fmaxf(acc, 0.f) * W2[j];
    __syncthreads();

    if (j == 0) {
        float s = b2[0];
        #pragma unroll
        for (int k = 0; k < 64; ++k) s += red[k];
        out[b] = 1.f / (1.f + expf(-s));
    }
}

// =====================================================================
extern "C" void kernel_launch(void* const* d_in, const int* in_sizes, int n_in,
                              void* d_out, int out_size) {
    const int*   x     = (const int*)d_in[0];
    const float* table = (const float*)d_in[1];
    const float* Wih_f = (const float*)d_in[2];
    const float* Whh_f = (const float*)d_in[3];
    const float* bih_f = (const float*)d_in[4];
    const float* bhh_f = (const float*)d_in[5];
    const float* Wih_b = (const float*)d_in[6];
    const float* Whh_b = (const float*)d_in[7];
    const float* bih_b = (const float*)d_in[8];
    const float* bhh_b = (const float*)d_in[9];
    const float* W1    = (const float*)d_in[10];
    const float* b1    = (const float*)d_in[11];
    const float* W2    = (const float*)d_in[12];
    const float* b2    = (const float*)d_in[13];
    float* out = (float*)d_out;

    cudaFuncSetAttribute(proj_kernel, cudaFuncAttributeMaxDynamicSharedMemorySize, PJ_SMEM);
    cudaFuncSetAttribute(scan_kernel, cudaFuncAttributeMaxDynamicSharedMemorySize, SC_SMEM);

    dim3 pg(4, 2 * TLEN);
    proj_kernel<<<pg, 256, PJ_SMEM>>>(x, table, Wih_f, bih_f, bhh_f, Wih_b, bih_b, bhh_b);
    scan_kernel<<<32, 256, SC_SMEM>>>(Whh_f, Whh_b);
    mlp_kernel<<<128, 64>>>(W1, b1, W2, b2, out);
}

// round 8
// speedup vs baseline: 4.7780x; 1.2970x over previous
#include <cuda_runtime.h>
#include <cuda_fp16.h>
#include <cstdint>
#include <cstddef>

#define TLEN  512
#define BATCH 128
#define EDIM  128
#define HDIM  128
#define GDIM  512   // 4*H
#define VOCAB 100000

// Scratch (device globals — no allocation).
// xp layout: [dir][t][slice(16)][g(512)][8b]  fp16
static __device__ __half g_xp[(size_t)2 * TLEN * 16 * GDIM * 8];
static __device__ __align__(16) __half g_table_h[(size_t)VOCAB * EDIM];
static __device__ __align__(16) __half g_wih_h[2 * GDIM * EDIM];
static __device__ float g_pool[2 * BATCH * HDIM];

// ---------- helpers ----------
#define H_HALF2 0x38003800u   // {0.5,0.5} fp16
__device__ __forceinline__ unsigned hmul2(unsigned a, unsigned b) {
    unsigned d; asm("mul.rn.f16x2 %0,%1,%2;" : "=r"(d) : "r"(a), "r"(b)); return d;
}
__device__ __forceinline__ unsigned hfma2(unsigned a, unsigned b, unsigned c) {
    unsigned d; asm("fma.rn.f16x2 %0,%1,%2,%3;" : "=r"(d) : "r"(a), "r"(b), "r"(c)); return d;
}
__device__ __forceinline__ unsigned htanh2(unsigned a) {
    unsigned d; asm("tanh.approx.f16x2 %0,%1;" : "=r"(d) : "r"(a)); return d;
}
__device__ __forceinline__ unsigned hsig2(unsigned x) {   // 0.5*tanh(0.5x)+0.5
    return hfma2(htanh2(hmul2(x, H_HALF2)), H_HALF2, H_HALF2);
}
__device__ __forceinline__ unsigned hmax2u(unsigned a, unsigned b) {
    __half2 r = __hmax2(*(__half2*)&a, *(__half2*)&b);
    return *(unsigned*)&r;
}
__device__ __forceinline__ float2 h22f2(unsigned v) {
    return __half22float2(*(__half2*)&v);
}
__device__ __forceinline__ unsigned f22h2(float lo, float hi) {   // lo in low half
    unsigned r; asm("cvt.rn.f16x2.f32 %0, %1, %2;" : "=r"(r) : "f"(hi), "f"(lo)); return r;
}
__device__ __forceinline__ unsigned dup_h2(float v) {
    __half2 h = __half2half2(__float2half_rn(v));
    return *(unsigned*)&h;
}
__device__ __forceinline__ unsigned sptr(const void* p) {
    return (unsigned)__cvta_generic_to_shared(p);
}
__device__ __forceinline__ void cpa16(void* s, const void* g) {
    asm volatile("cp.async.cg.shared.global [%0], [%1], 16;" :: "r"(sptr(s)), "l"(g));
}
__device__ __forceinline__ void mmaf16(unsigned& d0, unsigned& d1,
                                       unsigned a0, unsigned a1, unsigned a2, unsigned a3,
                                       unsigned b0, unsigned b1) {
    asm("mma.sync.aligned.m16n8k16.row.col.f16.f16.f16.f16 "
        "{%0,%1},{%2,%3,%4,%5},{%6,%7},{%0,%1};"
        : "+r"(d0), "+r"(d1)
        : "r"(a0), "r"(a1), "r"(a2), "r"(a3), "r"(b0), "r"(b1));
}
__device__ __forceinline__ void ldsm4(unsigned& r0, unsigned& r1, unsigned& r2, unsigned& r3,
                                      unsigned addr) {
    asm volatile("ldmatrix.sync.aligned.m8n8.x4.shared.b16 {%0,%1,%2,%3}, [%4];"
                 : "=r"(r0), "=r"(r1), "=r"(r2), "=r"(r3) : "r"(addr));
}
__device__ __forceinline__ void ldsm4t(unsigned& r0, unsigned& r1, unsigned& r2, unsigned& r3,
                                       unsigned addr) {
    asm volatile("ldmatrix.sync.aligned.m8n8.x4.trans.shared.b16 {%0,%1,%2,%3}, [%4];"
                 : "=r"(r0), "=r"(r1), "=r"(r2), "=r"(r3) : "r"(addr));
}

// =====================================================================
// Kernel 0a/0b: one-time fp32 -> fp16 conversions (per launch, ~12us)
// =====================================================================
__global__ void __launch_bounds__(256) conv_table_kernel(const float* __restrict__ t) {
    const size_t i = ((size_t)blockIdx.x * 256 + threadIdx.x) * 4;
    const float4 v = *(const float4*)(t + i);
    const __half2 a = __floats2half2_rn(v.x, v.y);
    const __half2 b = __floats2half2_rn(v.z, v.w);
    *(uint2*)&g_table_h[i] = make_uint2(*(const unsigned*)&a, *(const unsigned*)&b);
}
__global__ void __launch_bounds__(256) conv_wih_kernel(const float* __restrict__ wf,
                                                       const float* __restrict__ wb) {
    const int i = (blockIdx.x * 256 + threadIdx.x) * 4;   // i in [0, 65536)
    {
        const float4 v = *(const float4*)(wf + i);
        const __half2 a = __floats2half2_rn(v.x, v.y);
        const __half2 b = __floats2half2_rn(v.z, v.w);
        *(uint2*)&g_wih_h[i] = make_uint2(*(const unsigned*)&a, *(const unsigned*)&b);
    }
    {
        const float4 v = *(const float4*)(wb + i);
        const __half2 a = __floats2half2_rn(v.x, v.y);
        const __half2 b = __floats2half2_rn(v.z, v.w);
        *(uint2*)&g_wih_h[GDIM * EDIM + i] = make_uint2(*(const unsigned*)&a, *(const unsigned*)&b);
    }
}

// =====================================================================
// Kernel 1: input projection, fp16 mma (f16 accum) + cp.async + ldmatrix.
// C[g=128][b=128] = Wih_tile[g][e] * embT[e][b] + bias -> fp16 xp.
// grid=(4 gtiles, 2*512), 256 thr; warp tile 32g x 64b (wg=w&3, wb=w>>2).
// =====================================================================
#define PJ_STRIDE 136   // halves per smem row (272B, 16B-aligned, ldsm conflict-free)
#define PJ_SMEM (2 * 128 * PJ_STRIDE * 2)   // 69632 B

__global__ void __launch_bounds__(256, 2) proj_kernel(
    const int* __restrict__ x,
    const float* __restrict__ bih_f, const float* __restrict__ bhh_f,
    const float* __restrict__ bih_b, const float* __restrict__ bhh_b)
{
    extern __shared__ char dynsm[];
    __half* Wsm = (__half*)dynsm;             // [128][136]
    __half* Esm = Wsm + 128 * PJ_STRIDE;      // [128][136]
    __shared__ float bias_s[128];

    const int tid  = threadIdx.x, lane = tid & 31, w = tid >> 5;
    const int gtile = blockIdx.x;
    const int dir   = blockIdx.y >> 9;
    const int t     = blockIdx.y & 511;
    const float* bi  = dir ? bih_b : bih_f;
    const float* bh  = dir ? bhh_b : bhh_f;
    const int tsrc   = dir ? (TLEN - 1 - t) : t;

    if (tid < 128) {
        const int gg = gtile * 128 + tid;
        bias_s[tid] = bi[gg] + bh[gg];
    }

    // cp.async loads: E rows gathered by token; W rows from pre-converted fp16
    const __half* wsrc = g_wih_h + (size_t)(dir * GDIM + gtile * 128) * EDIM;
    #pragma unroll
    for (int it = 0; it < 8; ++it) {
        const int idx = it * 256 + tid;
        const int rb = idx >> 4, ch = idx & 15;
        const int tok = __ldg(&x[rb * TLEN + tsrc]);
        cpa16(&Esm[rb * PJ_STRIDE + ch * 8], g_table_h + (size_t)tok * EDIM + ch * 8);
    }
    #pragma unroll
    for (int it = 0; it < 8; ++it) {
        const int idx = it * 256 + tid;
        const int rg = idx >> 4, ch = idx & 15;
        cpa16(&Wsm[rg * PJ_STRIDE + ch * 8], wsrc + (size_t)rg * EDIM + ch * 8);
    }
    asm volatile("cp.async.commit_group;");
    asm volatile("cp.async.wait_group 0;" ::: "memory");
    __syncthreads();

    const int li = lane & 7, grp = lane >> 3;
    const int wg = w & 3, wb = w >> 2;
    const int gbase = wg * 32;
    const int row = lane >> 2, kq = (lane & 3) * 2;

    // D init with bias (f16x2)
    unsigned D[2][8][2];
    #pragma unroll
    for (int m = 0; m < 2; ++m) {
        const unsigned hb0 = dup_h2(bias_s[gbase + m * 16 + row]);
        const unsigned hb1 = dup_h2(bias_s[gbase + m * 16 + row + 8]);
        #pragma unroll
        for (int nt = 0; nt < 8; ++nt) { D[m][nt][0] = hb0; D[m][nt][1] = hb1; }
    }

    #pragma unroll
    for (int p = 0; p < 4; ++p) {
        // A frags for kt=2p,2p+1, both m-tiles
        unsigned A[2][2][4];
        #pragma unroll
        for (int m = 0; m < 2; ++m) {
            const unsigned abase = sptr(Wsm) +
                (((gbase + m * 16 + (grp & 1) * 8 + li) * PJ_STRIDE + (grp >> 1) * 8) << 1);
            ldsm4(A[m][0][0], A[m][0][1], A[m][0][2], A[m][0][3], abase + (2 * p) * 32);
            ldsm4(A[m][1][0], A[m][1][1], A[m][1][2], A[m][1][3], abase + (2 * p + 1) * 32);
        }
        #pragma unroll
        for (int nt = 0; nt < 8; ++nt) {
            unsigned b0a, b1a, b0b, b1b;
            const unsigned eb = sptr(Esm) +
                (((wb * 64 + nt * 8 + li) * PJ_STRIDE + grp * 8) << 1) + p * 64;
            ldsm4(b0a, b1a, b0b, b1b, eb);
            #pragma unroll
            for (int m = 0; m < 2; ++m) {
                mmaf16(D[m][nt][0], D[m][nt][1],
                       A[m][0][0], A[m][0][1], A[m][0][2], A[m][0][3], b0a, b1a);
                mmaf16(D[m][nt][0], D[m][nt][1],
                       A[m][1][0], A[m][1][1], A[m][1][2], A[m][1][3], b0b, b1b);
            }
        }
    }

    // store to xp [dir][t][slice][g][8]
    __half* base = g_xp + (size_t)(dir * TLEN + t) * 16 * GDIM * 8;
    #pragma unroll
    for (int m = 0; m < 2; ++m) {
        const int g0 = gtile * 128 + gbase + m * 16 + row;
        #pragma unroll
        for (int nt = 0; nt < 8; ++nt) {
            const int slice = wb * 8 + nt;
            __half* o = base + ((size_t)slice * GDIM) * 8 + kq;
            *(unsigned*)(o + (size_t)g0 * 8)       = D[m][nt][0];
            *(unsigned*)(o + (size_t)(g0 + 8) * 8) = D[m][nt][1];
        }
    }
}

// =====================================================================
// Kernel 2: fused-gate LSTM scan, f16 accum. 32 CTAs = 2 dir x 16 slices.
// 8 warps; warp w owns u in [16w,16w+16) for all 4 gates -> c,h,hmax in
// regs, 1 barrier/step. h ping-pong [u][8b] fp16 via ldmatrix.x4.trans.
// =====================================================================
#define SC_WSTRIDE 136
#define SC_SMEM (512 * SC_WSTRIDE * 2)   // 139264 B dynamic

__global__ void __launch_bounds__(256, 1) scan_kernel(
    const float* __restrict__ Whh_f, const float* __restrict__ Whh_b)
{
    extern __shared__ char dynsm[];
    __half* Wsm = (__half*)dynsm;   // [512][136]
    __shared__ __align__(16) __half h_pp[2][HDIM][8];

    const int tid  = threadIdx.x, lane = tid & 31, w = tid >> 5;
    const int dir  = blockIdx.x >> 4;
    const int slice = blockIdx.x & 15;
    const float* Whh = dir ? Whh_b : Whh_f;

    // Whh -> fp16 smem
    #pragma unroll 4
    for (int it = 0; it < 64; ++it) {
        const int idx = it * 256 + tid;
        const int rw = idx >> 5, q = idx & 31;
        const float4 v = __ldg((const float4*)(Whh + (size_t)rw * HDIM) + q);
        const __half2 a = __floats2half2_rn(v.x, v.y);
        const __half2 b = __floats2half2_rn(v.z, v.w);
        *(uint2*)&Wsm[rw * SC_WSTRIDE + q * 4] =
            make_uint2(*(const unsigned*)&a, *(const unsigned*)&b);
    }
    for (int i = tid; i < 2 * HDIM * 8; i += 256) ((__half*)h_pp)[i] = __float2half(0.f);
    __syncthreads();

    // A frags: 4 gates x 8 kt (loop-invariant, 128 regs)
    const int li = lane & 7, grp = lane >> 3;
    unsigned A[4][8][4];
    #pragma unroll
    for (int q = 0; q < 4; ++q) {
        const unsigned base = sptr(Wsm) +
            (((q * 128 + w * 16 + (grp & 1) * 8 + li) * SC_WSTRIDE + (grp >> 1) * 8) << 1);
        #pragma unroll
        for (int kt = 0; kt < 8; ++kt)
            ldsm4(A[q][kt][0], A[q][kt][1], A[q][kt][2], A[q][kt][3], base + kt * 32);
    }

    const int ur = w * 16 + (lane >> 2);
    const int cb = (lane & 3) * 2;
    const __half* xpd = g_xp + (size_t)dir * TLEN * 16 * GDIM * 8;
    size_t off[4];
    #pragma unroll
    for (int q = 0; q < 4; ++q)
        off[q] = ((size_t)slice * GDIM + q * 128 + ur) * 8 + cb;

    unsigned px0[4], px1[4];
    #pragma unroll
    for (int q = 0; q < 4; ++q) {
        px0[q] = *(const unsigned*)(xpd + off[q]);
        px1[q] = *(const unsigned*)(xpd + off[q] + 64);
    }

    float cst[4] = {0.f, 0.f, 0.f, 0.f};
    unsigned hm0 = 0xFC00FC00u, hm1 = 0xFC00FC00u;   // -inf fp16 x2

    for (int t = 0; t < TLEN; ++t) {
        unsigned D[4][2];
        #pragma unroll
        for (int q = 0; q < 4; ++q) { D[q][0] = px0[q]; D[q][1] = px1[q]; }

        const __half* xn = xpd + (size_t)((t + 1 < TLEN) ? t + 1 : t) * 16 * GDIM * 8;
        #pragma unroll
        for (int q = 0; q < 4; ++q) {
            px0[q] = *(const unsigned*)(xn + off[q]);
            px1[q] = *(const unsigned*)(xn + off[q] + 64);
        }

        // B frags from h ping buffer
        unsigned B[8][2];
        const unsigned hbase = sptr(&h_pp[t & 1][0][0]) + lane * 16;
        #pragma unroll
        for (int j = 0; j < 4; ++j)
            ldsm4t(B[2*j][0], B[2*j][1], B[2*j+1][0], B[2*j+1][1], hbase + j * 512);

        #pragma unroll
        for (int kt = 0; kt < 8; ++kt)
            #pragma unroll
            for (int q = 0; q < 4; ++q)
                mmaf16(D[q][0], D[q][1],
                       A[q][kt][0], A[q][kt][1], A[q][kt][2], A[q][kt][3],
                       B[kt][0], B[kt][1]);

        // activations: packed f16x2; c stays fp32
        const unsigned I0 = hsig2(D[0][0]),  I1 = hsig2(D[0][1]);
        const unsigned F0 = hsig2(D[1][0]),  F1 = hsig2(D[1][1]);
        const unsigned G0 = htanh2(D[2][0]), G1 = htanh2(D[2][1]);
        const unsigned O0 = hsig2(D[3][0]),  O1 = hsig2(D[3][1]);

        const float2 i0 = h22f2(I0), i1 = h22f2(I1);
        const float2 f0 = h22f2(F0), f1 = h22f2(F1);
        const float2 g0 = h22f2(G0), g1 = h22f2(G1);
        cst[0] = f0.x * cst[0] + i0.x * g0.x;
        cst[1] = f0.y * cst[1] + i0.y * g0.y;
        cst[2] = f1.x * cst[2] + i1.x * g1.x;
        cst[3] = f1.y * cst[3] + i1.y * g1.y;

        const unsigned T0 = htanh2(f22h2(cst[0], cst[1]));
        const unsigned T1 = htanh2(f22h2(cst[2], cst[3]));
        const unsigned H0 = hmul2(O0, T0);
        const unsigned H1 = hmul2(O1, T1);
        hm0 = hmax2u(hm0, H0);
        hm1 = hmax2u(hm1, H1);

        __half* hw = &h_pp[(t + 1) & 1][0][0];
        *(unsigned*)&hw[ur * 8 + cb]       = H0;
        *(unsigned*)&hw[(ur + 8) * 8 + cb] = H1;
        __syncthreads();
    }

    const float2 m0 = h22f2(hm0), m1 = h22f2(hm1);
    const int bb = slice * 8;
    g_pool[((size_t)dir * BATCH + bb + cb)     * HDIM + ur]     = m0.x;
    g_pool[((size_t)dir * BATCH + bb + cb + 1) * HDIM + ur]     = m0.y;
    g_pool[((size_t)dir * BATCH + bb + cb)     * HDIM + ur + 8] = m1.x;
    g_pool[((size_t)dir * BATCH + bb + cb + 1) * HDIM + ur + 8] = m1.y;
}

// =====================================================================
// Kernel 3: MLP head. grid=128 (batch), 64 threads (hidden units).
// =====================================================================
__global__ void __launch_bounds__(64) mlp_kernel(
    const float* __restrict__ W1, const float* __restrict__ b1,
    const float* __restrict__ W2, const float* __restrict__ b2,
    float* __restrict__ out)
{
    __shared__ __align__(16) float pv[256];
    __shared__ float red[64];
    const int b = blockIdx.x;
    const int j = threadIdx.x;

    for (int k = j; k < 256; k += 64) {
        const int dir = k >> 7, u = k & 127;
        pv[k] = g_pool[((size_t)dir * BATCH + b) * HDIM + u];
    }
    __syncthreads();

    float acc = b1[j];
    const float4* w4 = (const float4*)(W1 + (size_t)j * 256);
    const float4* p4 = (const float4*)pv;
    #pragma unroll 8
    for (int k = 0; k < 64; ++k) {
        const float4 wv = w4[k], p = p4[k];
        acc += wv.x * p.x + wv.y * p.y + wv.z * p.z + wv.w * p.w;
    }
    red[j] = fmaxf(acc, 0.f) * W2[j];
    __syncthreads();

    if (j == 0) {
        float s = b2[0];
        #pragma unroll
        for (int k = 0; k < 64; ++k) s += red[k];
        out[b] = 1.f / (1.f + expf(-s));
    }
}

// =====================================================================
extern "C" void kernel_launch(void* const* d_in, const int* in_sizes, int n_in,
                              void* d_out, int out_size) {
    const int*   x     = (const int*)d_in[0];
    const float* table = (const float*)d_in[1];
    const float* Wih_f = (const float*)d_in[2];
    const float* Whh_f = (const float*)d_in[3];
    const float* bih_f = (const float*)d_in[4];
    const float* bhh_f = (const float*)d_in[5];
    const float* Wih_b = (const float*)d_in[6];
    const float* Whh_b = (const float*)d_in[7];
    const float* bih_b = (const float*)d_in[8];
    const float* bhh_b = (const float*)d_in[9];
    const float* W1    = (const float*)d_in[10];
    const float* b1    = (const float*)d_in[11];
    const float* W2    = (const float*)d_in[12];
    const float* b2    = (const float*)d_in[13];
    float* out = (float*)d_out;

    cudaFuncSetAttribute(proj_kernel, cudaFuncAttributeMaxDynamicSharedMemorySize, PJ_SMEM);
    cudaFuncSetAttribute(scan_kernel, cudaFuncAttributeMaxDynamicSharedMemorySize, SC_SMEM);

    conv_table_kernel<<<(VOCAB * EDIM) / (256 * 4), 256>>>(table);
    conv_wih_kernel<<<(GDIM * EDIM) / (256 * 4), 256>>>(Wih_f, Wih_b);

    dim3 pg(4, 2 * TLEN);
    proj_kernel<<<pg, 256, PJ_SMEM>>>(x, bih_f, bhh_f, bih_b, bhh_b);
    scan_kernel<<<32, 256, SC_SMEM>>>(Whh_f, Whh_b);
    mlp_kernel<<<128, 64>>>(W1, b1, W2, b2, out);
}

// round 9
// speedup vs baseline: 4.8800x; 1.0214x over previous
#include <cuda_runtime.h>
#include <cuda_fp16.h>
#include <cstdint>
#include <cstddef>

#define TLEN  512
#define BATCH 128
#define EDIM  128
#define HDIM  128
#define GDIM  512   // 4*H
#define VOCAB 100000

// Scratch (device globals — no allocation).
// xp layout: [dir][t][slice(16)][g(512)][8b]  fp16
static __device__ __half g_xp[(size_t)2 * TLEN * 16 * GDIM * 8];
static __device__ __align__(16) __half g_table_h[(size_t)VOCAB * EDIM];
static __device__ __align__(16) __half g_wih_h[2 * GDIM * EDIM];
static __device__ float g_pool[2 * BATCH * HDIM];

// ---------- helpers ----------
#define H_HALF2 0x38003800u   // {0.5,0.5} fp16
__device__ __forceinline__ unsigned hmul2(unsigned a, unsigned b) {
    unsigned d; asm("mul.rn.f16x2 %0,%1,%2;" : "=r"(d) : "r"(a), "r"(b)); return d;
}
__device__ __forceinline__ unsigned hadd2u(unsigned a, unsigned b) {
    unsigned d; asm("add.rn.f16x2 %0,%1,%2;" : "=r"(d) : "r"(a), "r"(b)); return d;
}
__device__ __forceinline__ unsigned hfma2(unsigned a, unsigned b, unsigned c) {
    unsigned d; asm("fma.rn.f16x2 %0,%1,%2,%3;" : "=r"(d) : "r"(a), "r"(b), "r"(c)); return d;
}
__device__ __forceinline__ unsigned htanh2(unsigned a) {
    unsigned d; asm("tanh.approx.f16x2 %0,%1;" : "=r"(d) : "r"(a)); return d;
}
__device__ __forceinline__ unsigned hsig2(unsigned x) {   // 0.5*tanh(0.5x)+0.5
    return hfma2(htanh2(hmul2(x, H_HALF2)), H_HALF2, H_HALF2);
}
__device__ __forceinline__ unsigned hmax2u(unsigned a, unsigned b) {
    __half2 r = __hmax2(*(__half2*)&a, *(__half2*)&b);
    return *(unsigned*)&r;
}
__device__ __forceinline__ float2 h22f2(unsigned v) {
    return __half22float2(*(__half2*)&v);
}
__device__ __forceinline__ unsigned dup_h2(float v) {
    __half2 h = __half2half2(__float2half_rn(v));
    return *(unsigned*)&h;
}
__device__ __forceinline__ unsigned sptr(const void* p) {
    return (unsigned)__cvta_generic_to_shared(p);
}
__device__ __forceinline__ void cpa16(void* s, const void* g) {
    asm volatile("cp.async.cg.shared.global [%0], [%1], 16;" :: "r"(sptr(s)), "l"(g));
}
__device__ __forceinline__ void mmaf16(unsigned& d0, unsigned& d1,
                                       unsigned a0, unsigned a1, unsigned a2, unsigned a3,
                                       unsigned b0, unsigned b1) {
    asm("mma.sync.aligned.m16n8k16.row.col.f16.f16.f16.f16 "
        "{%0,%1},{%2,%3,%4,%5},{%6,%7},{%0,%1};"
        : "+r"(d0), "+r"(d1)
        : "r"(a0), "r"(a1), "r"(a2), "r"(a3), "r"(b0), "r"(b1));
}
__device__ __forceinline__ void ldsm4(unsigned& r0, unsigned& r1, unsigned& r2, unsigned& r3,
                                      unsigned addr) {
    asm volatile("ldmatrix.sync.aligned.m8n8.x4.shared.b16 {%0,%1,%2,%3}, [%4];"
                 : "=r"(r0), "=r"(r1), "=r"(r2), "=r"(r3) : "r"(addr));
}
__device__ __forceinline__ void ldsm4t(unsigned& r0, unsigned& r1, unsigned& r2, unsigned& r3,
                                       unsigned addr) {
    asm volatile("ldmatrix.sync.aligned.m8n8.x4.trans.shared.b16 {%0,%1,%2,%3}, [%4];"
                 : "=r"(r0), "=r"(r1), "=r"(r2), "=r"(r3) : "r"(addr));
}

// =====================================================================
// Kernel 0a/0b: one-time fp32 -> fp16 conversions (per launch)
// =====================================================================
__global__ void __launch_bounds__(256) conv_table_kernel(const float* __restrict__ t) {
    const size_t i = ((size_t)blockIdx.x * 256 + threadIdx.x) * 4;
    const float4 v = *(const float4*)(t + i);
    const __half2 a = __floats2half2_rn(v.x, v.y);
    const __half2 b = __floats2half2_rn(v.z, v.w);
    *(uint2*)&g_table_h[i] = make_uint2(*(const unsigned*)&a, *(const unsigned*)&b);
}
__global__ void __launch_bounds__(256) conv_wih_kernel(const float* __restrict__ wf,
                                                       const float* __restrict__ wb) {
    const int i = (blockIdx.x * 256 + threadIdx.x) * 4;
    {
        const float4 v = *(const float4*)(wf + i);
        const __half2 a = __floats2half2_rn(v.x, v.y);
        const __half2 b = __floats2half2_rn(v.z, v.w);
        *(uint2*)&g_wih_h[i] = make_uint2(*(const unsigned*)&a, *(const unsigned*)&b);
    }
    {
        const float4 v = *(const float4*)(wb + i);
        const __half2 a = __floats2half2_rn(v.x, v.y);
        const __half2 b = __floats2half2_rn(v.z, v.w);
        *(uint2*)&g_wih_h[GDIM * EDIM + i] = make_uint2(*(const unsigned*)&a, *(const unsigned*)&b);
    }
}

// =====================================================================
// Kernel 1: input projection, fp16 mma (f16 accum) + cp.async + ldmatrix.
// =====================================================================
#define PJ_STRIDE 136
#define PJ_SMEM (2 * 128 * PJ_STRIDE * 2)   // 69632 B

__global__ void __launch_bounds__(256, 2) proj_kernel(
    const int* __restrict__ x,
    const float* __restrict__ bih_f, const float* __restrict__ bhh_f,
    const float* __restrict__ bih_b, const float* __restrict__ bhh_b)
{
    extern __shared__ char dynsm[];
    __half* Wsm = (__half*)dynsm;             // [128][136]
    __half* Esm = Wsm + 128 * PJ_STRIDE;      // [128][136]
    __shared__ float bias_s[128];

    const int tid  = threadIdx.x, lane = tid & 31, w = tid >> 5;
    const int gtile = blockIdx.x;
    const int dir   = blockIdx.y >> 9;
    const int t     = blockIdx.y & 511;
    const float* bi  = dir ? bih_b : bih_f;
    const float* bh  = dir ? bhh_b : bhh_f;
    const int tsrc   = dir ? (TLEN - 1 - t) : t;

    if (tid < 128) {
        const int gg = gtile * 128 + tid;
        bias_s[tid] = bi[gg] + bh[gg];
    }

    const __half* wsrc = g_wih_h + (size_t)(dir * GDIM + gtile * 128) * EDIM;
    #pragma unroll
    for (int it = 0; it < 8; ++it) {
        const int idx = it * 256 + tid;
        const int rb = idx >> 4, ch = idx & 15;
        const int tok = __ldg(&x[rb * TLEN + tsrc]);
        cpa16(&Esm[rb * PJ_STRIDE + ch * 8], g_table_h + (size_t)tok * EDIM + ch * 8);
    }
    #pragma unroll
    for (int it = 0; it < 8; ++it) {
        const int idx = it * 256 + tid;
        const int rg = idx >> 4, ch = idx & 15;
        cpa16(&Wsm[rg * PJ_STRIDE + ch * 8], wsrc + (size_t)rg * EDIM + ch * 8);
    }
    asm volatile("cp.async.commit_group;");
    asm volatile("cp.async.wait_group 0;" ::: "memory");
    __syncthreads();

    const int li = lane & 7, grp = lane >> 3;
    const int wg = w & 3, wb = w >> 2;
    const int gbase = wg * 32;
    const int row = lane >> 2, kq = (lane & 3) * 2;

    unsigned D[2][8][2];
    #pragma unroll
    for (int m = 0; m < 2; ++m) {
        const unsigned hb0 = dup_h2(bias_s[gbase + m * 16 + row]);
        const unsigned hb1 = dup_h2(bias_s[gbase + m * 16 + row + 8]);
        #pragma unroll
        for (int nt = 0; nt < 8; ++nt) { D[m][nt][0] = hb0; D[m][nt][1] = hb1; }
    }

    #pragma unroll
    for (int p = 0; p < 4; ++p) {
        unsigned A[2][2][4];
        #pragma unroll
        for (int m = 0; m < 2; ++m) {
            const unsigned abase = sptr(Wsm) +
                (((gbase + m * 16 + (grp & 1) * 8 + li) * PJ_STRIDE + (grp >> 1) * 8) << 1);
            ldsm4(A[m][0][0], A[m][0][1], A[m][0][2], A[m][0][3], abase + (2 * p) * 32);
            ldsm4(A[m][1][0], A[m][1][1], A[m][1][2], A[m][1][3], abase + (2 * p + 1) * 32);
        }
        #pragma unroll
        for (int nt = 0; nt < 8; ++nt) {
            unsigned b0a, b1a, b0b, b1b;
            const unsigned eb = sptr(Esm) +
                (((wb * 64 + nt * 8 + li) * PJ_STRIDE + grp * 8) << 1) + p * 64;
            ldsm4(b0a, b1a, b0b, b1b, eb);
            #pragma unroll
            for (int m = 0; m < 2; ++m) {
                mmaf16(D[m][nt][0], D[m][nt][1],
                       A[m][0][0], A[m][0][1], A[m][0][2], A[m][0][3], b0a, b1a);
                mmaf16(D[m][nt][0], D[m][nt][1],
                       A[m][1][0], A[m][1][1], A[m][1][2], A[m][1][3], b0b, b1b);
            }
        }
    }

    __half* base = g_xp + (size_t)(dir * TLEN + t) * 16 * GDIM * 8;
    #pragma unroll
    for (int m = 0; m < 2; ++m) {
        const int g0 = gtile * 128 + gbase + m * 16 + row;
        #pragma unroll
        for (int nt = 0; nt < 8; ++nt) {
            const int slice = wb * 8 + nt;
            __half* o = base + ((size_t)slice * GDIM) * 8 + kq;
            *(unsigned*)(o + (size_t)g0 * 8)       = D[m][nt][0];
            *(unsigned*)(o + (size_t)(g0 + 8) * 8) = D[m][nt][1];
        }
    }
}

// =====================================================================
// Kernel 2: fused-gate LSTM scan, f16 accum, split chains, packed update.
// 32 CTAs = 2 dir x 16 slices; 8 warps; warp w owns u in [16w,16w+16).
// Two 4-deep mma chains per gate (D: kt0-3, E: kt4-7) -> 8 independent
// chains/warp; c held in f16x2 regs; whole update packed f16x2.
// =====================================================================
#define SC_WSTRIDE 136
#define SC_SMEM (512 * SC_WSTRIDE * 2)   // 139264 B dynamic

__global__ void __launch_bounds__(256, 1) scan_kernel(
    const float* __restrict__ Whh_f, const float* __restrict__ Whh_b)
{
    extern __shared__ char dynsm[];
    __half* Wsm = (__half*)dynsm;   // [512][136]
    __shared__ __align__(16) __half h_pp[2][HDIM][8];

    const int tid  = threadIdx.x, lane = tid & 31, w = tid >> 5;
    const int dir  = blockIdx.x >> 4;
    const int slice = blockIdx.x & 15;
    const float* Whh = dir ? Whh_b : Whh_f;

    #pragma unroll 4
    for (int it = 0; it < 64; ++it) {
        const int idx = it * 256 + tid;
        const int rw = idx >> 5, q = idx & 31;
        const float4 v = __ldg((const float4*)(Whh + (size_t)rw * HDIM) + q);
        const __half2 a = __floats2half2_rn(v.x, v.y);
        const __half2 b = __floats2half2_rn(v.z, v.w);
        *(uint2*)&Wsm[rw * SC_WSTRIDE + q * 4] =
            make_uint2(*(const unsigned*)&a, *(const unsigned*)&b);
    }
    for (int i = tid; i < 2 * HDIM * 8; i += 256) ((__half*)h_pp)[i] = __float2half(0.f);
    __syncthreads();

    const int li = lane & 7, grp = lane >> 3;
    unsigned A[4][8][4];
    #pragma unroll
    for (int q = 0; q < 4; ++q) {
        const unsigned base = sptr(Wsm) +
            (((q * 128 + w * 16 + (grp & 1) * 8 + li) * SC_WSTRIDE + (grp >> 1) * 8) << 1);
        #pragma unroll
        for (int kt = 0; kt < 8; ++kt)
            ldsm4(A[q][kt][0], A[q][kt][1], A[q][kt][2], A[q][kt][3], base + kt * 32);
    }

    const int ur = w * 16 + (lane >> 2);
    const int cb = (lane & 3) * 2;
    const __half* xpd = g_xp + (size_t)dir * TLEN * 16 * GDIM * 8;
    size_t off[4];
    #pragma unroll
    for (int q = 0; q < 4; ++q)
        off[q] = ((size_t)slice * GDIM + q * 128 + ur) * 8 + cb;

    unsigned px0[4], px1[4];
    #pragma unroll
    for (int q = 0; q < 4; ++q) {
        px0[q] = *(const unsigned*)(xpd + off[q]);
        px1[q] = *(const unsigned*)(xpd + off[q] + 64);
    }

    unsigned c20 = 0u, c21 = 0u;                      // f16x2 cell state
    unsigned hm0 = 0xFC00FC00u, hm1 = 0xFC00FC00u;    // -inf f16x2 running max

    for (int t = 0; t < TLEN; ++t) {
        // B frags first (ready before mma)
        unsigned B[8][2];
        const unsigned hbase = sptr(&h_pp[t & 1][0][0]) + lane * 16;
        #pragma unroll
        for (int j = 0; j < 4; ++j)
            ldsm4t(B[2*j][0], B[2*j][1], B[2*j+1][0], B[2*j+1][1], hbase + j * 512);

        // split accumulators: D <- xp + kt0..3,  E <- 0 + kt4..7
        unsigned D[4][2], E[4][2];
        #pragma unroll
        for (int q = 0; q < 4; ++q) {
            D[q][0] = px0[q]; D[q][1] = px1[q];
            E[q][0] = 0u;     E[q][1] = 0u;
        }

        // prefetch next xp (overlaps mma)
        const __half* xn = xpd + (size_t)((t + 1 < TLEN) ? t + 1 : t) * 16 * GDIM * 8;
        #pragma unroll
        for (int q = 0; q < 4; ++q) {
            px0[q] = *(const unsigned*)(xn + off[q]);
            px1[q] = *(const unsigned*)(xn + off[q] + 64);
        }

        // 8 independent 4-deep chains, interleaved
        #pragma unroll
        for (int kt = 0; kt < 4; ++kt) {
            #pragma unroll
            for (int q = 0; q < 4; ++q) {
                mmaf16(D[q][0], D[q][1],
                       A[q][kt][0], A[q][kt][1], A[q][kt][2], A[q][kt][3],
                       B[kt][0], B[kt][1]);
                mmaf16(E[q][0], E[q][1],
                       A[q][kt+4][0], A[q][kt+4][1], A[q][kt+4][2], A[q][kt+4][3],
                       B[kt+4][0], B[kt+4][1]);
            }
        }
        unsigned P[4][2];
        #pragma unroll
        for (int q = 0; q < 4; ++q) {
            P[q][0] = hadd2u(D[q][0], E[q][0]);
            P[q][1] = hadd2u(D[q][1], E[q][1]);
        }

        // fully packed f16x2 update; c in f16x2
        const unsigned I0 = hsig2(P[0][0]),  I1 = hsig2(P[0][1]);
        const unsigned F0 = hsig2(P[1][0]),  F1 = hsig2(P[1][1]);
        const unsigned G0 = htanh2(P[2][0]), G1 = htanh2(P[2][1]);
        const unsigned O0 = hsig2(P[3][0]),  O1 = hsig2(P[3][1]);

        c20 = hfma2(F0, c20, hmul2(I0, G0));
        c21 = hfma2(F1, c21, hmul2(I1, G1));
        const unsigned H0 = hmul2(O0, htanh2(c20));
        const unsigned H1 = hmul2(O1, htanh2(c21));
        hm0 = hmax2u(hm0, H0);
        hm1 = hmax2u(hm1, H1);

        __half* hw = &h_pp[(t + 1) & 1][0][0];
        *(unsigned*)&hw[ur * 8 + cb]       = H0;
        *(unsigned*)&hw[(ur + 8) * 8 + cb] = H1;
        __syncthreads();
    }

    const float2 m0 = h22f2(hm0), m1 = h22f2(hm1);
    const int bb = slice * 8;
    g_pool[((size_t)dir * BATCH + bb + cb)     * HDIM + ur]     = m0.x;
    g_pool[((size_t)dir * BATCH + bb + cb + 1) * HDIM + ur]     = m0.y;
    g_pool[((size_t)dir * BATCH + bb + cb)     * HDIM + ur + 8] = m1.x;
    g_pool[((size_t)dir * BATCH + bb + cb + 1) * HDIM + ur + 8] = m1.y;
}

// =====================================================================
// Kernel 3: MLP head.
// =====================================================================
__global__ void __launch_bounds__(64) mlp_kernel(
    const float* __restrict__ W1, const float* __restrict__ b1,
    const float* __restrict__ W2, const float* __restrict__ b2,
    float* __restrict__ out)
{
    __shared__ __align__(16) float pv[256];
    __shared__ float red[64];
    const int b = blockIdx.x;
    const int j = threadIdx.x;

    for (int k = j; k < 256; k += 64) {
        const int dir = k >> 7, u = k & 127;
        pv[k] = g_pool[((size_t)dir * BATCH + b) * HDIM + u];
    }
    __syncthreads();

    float acc = b1[j];
    const float4* w4 = (const float4*)(W1 + (size_t)j * 256);
    const float4* p4 = (const float4*)pv;
    #pragma unroll 8
    for (int k = 0; k < 64; ++k) {
        const float4 wv = w4[k], p = p4[k];
        acc += wv.x * p.x + wv.y * p.y + wv.z * p.z + wv.w * p.w;
    }
    red[j] = fmaxf(acc, 0.f) * W2[j];
    __syncthreads();

    if (j == 0) {
        float s = b2[0];
        #pragma unroll
        for (int k = 0; k < 64; ++k) s += red[k];
        out[b] = 1.f / (1.f + expf(-s));
    }
}

// =====================================================================
extern "C" void kernel_launch(void* const* d_in, const int* in_sizes, int n_in,
                              void* d_out, int out_size) {
    const int*   x     = (const int*)d_in[0];
    const float* table = (const float*)d_in[1];
    const float* Wih_f = (const float*)d_in[2];
    const float* Whh_f = (const float*)d_in[3];
    const float* bih_f = (const float*)d_in[4];
    const float* bhh_f = (const float*)d_in[5];
    const float* Wih_b = (const float*)d_in[6];
    const float* Whh_b = (const float*)d_in[7];
    const float* bih_b = (const float*)d_in[8];
    const float* bhh_b = (const float*)d_in[9];
    const float* W1    = (const float*)d_in[10];
    const float* b1    = (const float*)d_in[11];
    const float* W2    = (const float*)d_in[12];
    const float* b2    = (const float*)d_in[13];
    float* out = (float*)d_out;

    cudaFuncSetAttribute(proj_kernel, cudaFuncAttributeMaxDynamicSharedMemorySize, PJ_SMEM);
    cudaFuncSetAttribute(scan_kernel, cudaFuncAttributeMaxDynamicSharedMemorySize, SC_SMEM);

    conv_table_kernel<<<(VOCAB * EDIM) / (256 * 4), 256>>>(table);
    conv_wih_kernel<<<(GDIM * EDIM) / (256 * 4), 256>>>(Wih_f, Wih_b);

    dim3 pg(4, 2 * TLEN);
    proj_kernel<<<pg, 256, PJ_SMEM>>>(x, bih_f, bhh_f, bih_b, bhh_b);
    scan_kernel<<<32, 256, SC_SMEM>>>(Whh_f, Whh_b);
    mlp_kernel<<<128, 64>>>(W1, b1, W2, b2, out);
}